// round 2
// baseline (speedup 1.0000x reference)
#include <cuda_runtime.h>
#include <math.h>

// Problem dims (fixed by the reference)
#define NB     128        // batch
#define TS     32         // timesteps (captions T=33 -> 32 in/out)
#define DFEAT  1280
#define WDIM   256
#define HDIM   512
#define VS     32000
#define G4     2048       // 4*H
#define RTOT   4096       // TS*NB rows of hs
#define NVB    500        // VS/64 vocab chunks

// -------- scratch (device globals; no allocation allowed) --------
__device__ float g_h0[NB * HDIM];
__device__ float g_c[NB * HDIM];
__device__ float g_hs[TS * NB * HDIM];          // [t][n][h]
__device__ float g_xw[RTOT * G4];               // [(n*32+t)][4H] = x@Wx + b
__device__ float g_pmax[RTOT * NVB];
__device__ float g_psum[RTOT * NVB];
__device__ float g_block[512];
__device__ int   g_caps[NB * 33];               // decoded captions (int32)

// ---------------- decode captions: sniff int32 vs int64, normalize to int32 ----------------
// If the buffer is int64 (values < 32000, nonneg), every odd 32-bit word is 0.
// If int32, odd words are random tokens (virtually certain some are nonzero).
__global__ void decode_caps_kernel(const void* __restrict__ capsraw) {
    const int* w = (const int*)capsraw;
    int odd_nonzero = 0;
    for (int i = threadIdx.x; i < 256; i += blockDim.x)
        if (w[2 * i + 1] != 0) odd_nonzero = 1;
    odd_nonzero = __syncthreads_or(odd_nonzero);
    if (odd_nonzero) {
        // int32 delivery
        for (int i = threadIdx.x; i < NB * 33; i += blockDim.x)
            g_caps[i] = w[i];
    } else {
        // int64 delivery
        const long long* w64 = (const long long*)capsraw;
        for (int i = threadIdx.x; i < NB * 33; i += blockDim.x)
            g_caps[i] = (int)w64[i];
    }
}

// ---------------- zero c ----------------
__global__ void zero_c_kernel() {
    g_c[blockIdx.x * 1024 + threadIdx.x] = 0.0f;
}

// ---------------- generic 64x64 tiled SGEMM with optional embedding gather ----------------
// C[M,N] = A[M,K] @ B[K,N] + bias (row of length N)
// If caps != null: A row for global row r is W_embed row caps[(r>>5)*33 + (r&31)]
// Grid: (N/64, M/64), block 256. All dims divisible by 64/16 by construction.
__global__ void sgemm64_kernel(const float* __restrict__ A, const float* __restrict__ B,
                               const float* __restrict__ bias, float* __restrict__ C,
                               int N, int K, const int* __restrict__ caps)
{
    __shared__ float As[16][64];
    __shared__ float Bs[16][64];
    const int tid = threadIdx.x;
    const int bm = blockIdx.y * 64, bn = blockIdx.x * 64;
    const int tx = tid & 15, ty = tid >> 4;
    const int ar = tid >> 2, ak = (tid & 3) * 4;   // A loader: row ar, 4 consecutive k
    const int bk = tid >> 4, bn0 = (tid & 15) * 4; // B loader: k row bk, 4 consecutive n

    const int row = bm + ar;
    const int src = caps ? caps[(row >> 5) * 33 + (row & 31)] : row;
    const float* Arow = A + (size_t)src * K + ak;
    const float* Bp = B + (size_t)bk * N + bn + bn0;

    float acc[4][4] = {};
    for (int k0 = 0; k0 < K; k0 += 16) {
        float4 av = *(const float4*)(Arow + k0);
        As[ak + 0][ar] = av.x;
        As[ak + 1][ar] = av.y;
        As[ak + 2][ar] = av.z;
        As[ak + 3][ar] = av.w;
        *(float4*)&Bs[bk][bn0] = *(const float4*)(Bp + (size_t)k0 * N);
        __syncthreads();
#pragma unroll
        for (int k = 0; k < 16; k++) {
            float4 a = *(const float4*)&As[k][ty * 4];
            float4 b = *(const float4*)&Bs[k][tx * 4];
            acc[0][0] += a.x * b.x; acc[0][1] += a.x * b.y; acc[0][2] += a.x * b.z; acc[0][3] += a.x * b.w;
            acc[1][0] += a.y * b.x; acc[1][1] += a.y * b.y; acc[1][2] += a.y * b.z; acc[1][3] += a.y * b.w;
            acc[2][0] += a.z * b.x; acc[2][1] += a.z * b.y; acc[2][2] += a.z * b.z; acc[2][3] += a.z * b.w;
            acc[3][0] += a.w * b.x; acc[3][1] += a.w * b.y; acc[3][2] += a.w * b.z; acc[3][3] += a.w * b.w;
        }
        __syncthreads();
    }
    const int cn = bn + tx * 4;
    float4 bb = *(const float4*)(bias + cn);
#pragma unroll
    for (int i = 0; i < 4; i++) {
        float4 o;
        o.x = acc[i][0] + bb.x; o.y = acc[i][1] + bb.y;
        o.z = acc[i][2] + bb.z; o.w = acc[i][3] + bb.w;
        *(float4*)&C[(size_t)(bm + ty * 4 + i) * N + cn] = o;
    }
}

// ---------------- LSTM step: A = hprev@Wh + g_xw[:,t,:] -> gates -> c,h ----------------
// Grid: (512/32=16, 128/32=4), block 256. Tile: 32 rows(n) x 32 cols(j), 4 gates per cell.
__global__ void lstm_step_kernel(const float* __restrict__ Wh, int t)
{
    __shared__ float Hs[16][32];
    __shared__ float Wsm[16][128];   // [k][gate*32 + j]
    const int tid = threadIdx.x;
    const int jb = blockIdx.x * 32, nb = blockIdx.y * 32;
    const float* hprev = t ? (g_hs + (size_t)(t - 1) * NB * HDIM) : g_h0;
    float* hout = g_hs + (size_t)t * NB * HDIM;

    // loaders
    const int hr = tid >> 3, hk0 = (tid & 7) * 2;       // 32 rows x 2 k each
    const int wk = tid >> 4, wc0 = (tid & 15) * 8;      // 16 k rows x 8 cols each
    const int wg = wc0 >> 5, wj0 = wc0 & 31;
    // compute mapping
    const int ty = tid >> 4, tx = tid & 15;             // 16x16 -> 2x2 cells

    float acc[4][2][2] = {};  // [gate][row][col]
    for (int k0 = 0; k0 < HDIM; k0 += 16) {
        float2 hv = *(const float2*)(hprev + (size_t)(nb + hr) * HDIM + k0 + hk0);
        Hs[hk0 + 0][hr] = hv.x;
        Hs[hk0 + 1][hr] = hv.y;
        const float* wp = Wh + (size_t)(k0 + wk) * G4 + wg * HDIM + jb + wj0;
        *(float4*)&Wsm[wk][wc0]     = *(const float4*)(wp);
        *(float4*)&Wsm[wk][wc0 + 4] = *(const float4*)(wp + 4);
        __syncthreads();
#pragma unroll
        for (int k = 0; k < 16; k++) {
            float a0 = Hs[k][ty * 2], a1 = Hs[k][ty * 2 + 1];
#pragma unroll
            for (int g = 0; g < 4; g++) {
                float b0 = Wsm[k][g * 32 + tx * 2];
                float b1 = Wsm[k][g * 32 + tx * 2 + 1];
                acc[g][0][0] += a0 * b0; acc[g][0][1] += a0 * b1;
                acc[g][1][0] += a1 * b0; acc[g][1][1] += a1 * b1;
            }
        }
        __syncthreads();
    }
#pragma unroll
    for (int i = 0; i < 2; i++) {
#pragma unroll
        for (int jj = 0; jj < 2; jj++) {
            const int n = nb + ty * 2 + i;
            const int j = jb + tx * 2 + jj;
            const size_t xb = (size_t)(n * TS + t) * G4 + j;
            float Ai = acc[0][i][jj] + g_xw[xb];
            float Af = acc[1][i][jj] + g_xw[xb + 512];
            float Ao = acc[2][i][jj] + g_xw[xb + 1024];
            float Ag = acc[3][i][jj] + g_xw[xb + 1536];
            float si = 1.0f / (1.0f + expf(-Ai));
            float sf = 1.0f / (1.0f + expf(-Af));
            float so = 1.0f / (1.0f + expf(-Ao));
            float tg = tanhf(Ag);
            const int ci = n * HDIM + j;
            float cn = sf * g_c[ci] + si * tg;
            g_c[ci] = cn;
            hout[ci] = so * tanhf(cn);
        }
    }
}

// ---------------- vocab GEMM + per-chunk logsumexp partials ----------------
// Grid: (500, 64), block 256. Tile 64 rows x 64 vocab cols, K=512.
__global__ void vocab_kernel(const float* __restrict__ Wv, const float* __restrict__ bv)
{
    __shared__ float As[16][64];
    __shared__ float Bs[16][64];
    const int tid = threadIdx.x;
    const int bm = blockIdx.y * 64, bn = blockIdx.x * 64;
    const int tx = tid & 15, ty = tid >> 4;
    const int ar = tid >> 2, ak = (tid & 3) * 4;
    const int bk = tid >> 4, bn0 = (tid & 15) * 4;

    const float* Arow = g_hs + (size_t)(bm + ar) * HDIM + ak;
    const float* Bp = Wv + (size_t)bk * VS + bn + bn0;

    float acc[4][4] = {};
    for (int k0 = 0; k0 < HDIM; k0 += 16) {
        float4 av = *(const float4*)(Arow + k0);
        As[ak + 0][ar] = av.x;
        As[ak + 1][ar] = av.y;
        As[ak + 2][ar] = av.z;
        As[ak + 3][ar] = av.w;
        *(float4*)&Bs[bk][bn0] = *(const float4*)(Bp + (size_t)k0 * VS);
        __syncthreads();
#pragma unroll
        for (int k = 0; k < 16; k++) {
            float4 a = *(const float4*)&As[k][ty * 4];
            float4 b = *(const float4*)&Bs[k][tx * 4];
            acc[0][0] += a.x * b.x; acc[0][1] += a.x * b.y; acc[0][2] += a.x * b.z; acc[0][3] += a.x * b.w;
            acc[1][0] += a.y * b.x; acc[1][1] += a.y * b.y; acc[1][2] += a.y * b.z; acc[1][3] += a.y * b.w;
            acc[2][0] += a.z * b.x; acc[2][1] += a.z * b.y; acc[2][2] += a.z * b.z; acc[2][3] += a.z * b.w;
            acc[3][0] += a.w * b.x; acc[3][1] += a.w * b.y; acc[3][2] += a.w * b.z; acc[3][3] += a.w * b.w;
        }
        __syncthreads();
    }
    float4 bb = *(const float4*)(bv + bn + tx * 4);
#pragma unroll
    for (int i = 0; i < 4; i++) {
        float s0 = acc[i][0] + bb.x;
        float s1 = acc[i][1] + bb.y;
        float s2 = acc[i][2] + bb.z;
        float s3 = acc[i][3] + bb.w;
        float m = fmaxf(fmaxf(s0, s1), fmaxf(s2, s3));
#pragma unroll
        for (int off = 8; off; off >>= 1)
            m = fmaxf(m, __shfl_xor_sync(0xffffffffu, m, off, 16));
        float e = __expf(s0 - m) + __expf(s1 - m) + __expf(s2 - m) + __expf(s3 - m);
#pragma unroll
        for (int off = 8; off; off >>= 1)
            e += __shfl_xor_sync(0xffffffffu, e, off, 16);
        if (tx == 0) {
            const int r = bm + ty * 4 + i;
            g_pmax[r * NVB + blockIdx.x] = m;
            g_psum[r * NVB + blockIdx.x] = e;
        }
    }
}

// ---------------- per-row logsumexp combine + target score + per-CTA partial ----------------
// Grid: 512 CTAs x 256 threads; one warp per row (8 rows/CTA).
__global__ void reduce_kernel(const float* __restrict__ Wv, const float* __restrict__ bv)
{
    const int r = blockIdx.x * 8 + (threadIdx.x >> 5);
    const int lane = threadIdx.x & 31;

    float gm = -INFINITY;
    for (int k = lane; k < NVB; k += 32)
        gm = fmaxf(gm, g_pmax[r * NVB + k]);
#pragma unroll
    for (int off = 16; off; off >>= 1)
        gm = fmaxf(gm, __shfl_xor_sync(0xffffffffu, gm, off));

    float s = 0.0f;
    for (int k = lane; k < NVB; k += 32)
        s += g_psum[r * NVB + k] * expf(g_pmax[r * NVB + k] - gm);
#pragma unroll
    for (int off = 16; off; off >>= 1)
        s += __shfl_xor_sync(0xffffffffu, s, off);

    const int t = r >> 7, n = r & 127;
    const int tgt = g_caps[n * 33 + t + 1];
    float dot = 0.0f;
    for (int k = lane; k < HDIM; k += 32)
        dot += g_hs[(size_t)r * HDIM + k] * Wv[(size_t)k * VS + tgt];
#pragma unroll
    for (int off = 16; off; off >>= 1)
        dot += __shfl_xor_sync(0xffffffffu, dot, off);

    __shared__ float sm[8];
    if (lane == 0) {
        float lse = gm + logf(s);
        float nll = lse - (dot + bv[tgt]);
        sm[threadIdx.x >> 5] = (tgt != 0) ? nll : 0.0f;
    }
    __syncthreads();
    if (threadIdx.x == 0) {
        float tot = 0.0f;
#pragma unroll
        for (int i = 0; i < 8; i++) tot += sm[i];
        g_block[blockIdx.x] = tot;
    }
}

__global__ void final_kernel(float* __restrict__ out)
{
    __shared__ float sm[512];
    sm[threadIdx.x] = g_block[threadIdx.x];
    __syncthreads();
    for (int sstep = 256; sstep; sstep >>= 1) {
        if (threadIdx.x < sstep) sm[threadIdx.x] += sm[threadIdx.x + sstep];
        __syncthreads();
    }
    if (threadIdx.x == 0) out[0] = sm[0] / (float)NB;
}

// ---------------- host ----------------
extern "C" void kernel_launch(void* const* d_in, const int* in_sizes, int n_in,
                              void* d_out, int out_size)
{
    (void)in_sizes; (void)n_in; (void)out_size;
    const float* features = (const float*)d_in[0];
    const void*  captions = d_in[1];
    const float* W_proj   = (const float*)d_in[2];
    const float* b_proj   = (const float*)d_in[3];
    const float* W_embed  = (const float*)d_in[4];
    const float* Wx       = (const float*)d_in[5];
    const float* Wh       = (const float*)d_in[6];
    const float* b        = (const float*)d_in[7];
    const float* W_vocab  = (const float*)d_in[8];
    const float* b_vocab  = (const float*)d_in[9];

    float *h0p = nullptr, *xwp = nullptr;
    int *capsp = nullptr;
    cudaGetSymbolAddress((void**)&h0p, g_h0);
    cudaGetSymbolAddress((void**)&xwp, g_xw);
    cudaGetSymbolAddress((void**)&capsp, g_caps);

    decode_caps_kernel<<<1, 256>>>(captions);
    zero_c_kernel<<<64, 1024>>>();

    // h0 = features @ W_proj + b_proj   (M=128, K=1280, N=512)
    sgemm64_kernel<<<dim3(HDIM / 64, NB / 64), 256>>>(features, W_proj, b_proj, h0p,
                                                      HDIM, DFEAT, nullptr);
    // XW = embed(captions_in) @ Wx + b  (M=4096 rows (n*32+t), K=256, N=2048)
    sgemm64_kernel<<<dim3(G4 / 64, RTOT / 64), 256>>>(W_embed, Wx, b, xwp,
                                                      G4, WDIM, capsp);
    // sequential LSTM
    for (int t = 0; t < TS; t++)
        lstm_step_kernel<<<dim3(HDIM / 32, NB / 32), 256>>>(Wh, t);

    // fused vocab GEMM + chunked logsumexp
    vocab_kernel<<<dim3(NVB, RTOT / 64), 256>>>(W_vocab, b_vocab);

    // combine + target scores + deterministic reduction
    reduce_kernel<<<512, 256>>>(W_vocab, b_vocab);
    final_kernel<<<1, 512>>>((float*)d_out);
}

// round 3
// speedup vs baseline: 1.0011x; 1.0011x over previous
#include <cuda_runtime.h>
#include <math.h>

// Problem dims (fixed by the reference)
#define NB     128        // batch
#define TS     32         // timesteps (captions T=33 -> 32 in/out)
#define DFEAT  1280
#define WDIM   256
#define HDIM   512
#define VS     32000
#define G4     2048       // 4*H
#define RTOT   4096       // TS*NB rows of hs
#define NVB    500        // VS/64 vocab chunks

// -------- scratch (device globals; no allocation allowed) --------
__device__ float g_h0[NB * HDIM];
__device__ float g_c[NB * HDIM];
__device__ float g_hs[TS * NB * HDIM];          // [t][n][h]
__device__ float g_xw[RTOT * G4];               // [(n*32+t)][4H] = x@Wx + b
__device__ float g_pmax[RTOT * NVB];
__device__ float g_psum[RTOT * NVB];
__device__ float g_block[512];
__device__ int   g_caps[NB * 33];               // decoded captions (int32)

// ---------------- decode captions: sniff int32 vs int64, normalize to int32 ----------------
// If the buffer is int64 (values < 32000, nonneg), every odd 32-bit word is 0.
// If int32, odd words are random tokens (virtually certain some are nonzero).
__global__ void decode_caps_kernel(const void* __restrict__ capsraw) {
    const int* w = (const int*)capsraw;
    int odd_nonzero = 0;
    for (int i = threadIdx.x; i < 256; i += blockDim.x)
        if (w[2 * i + 1] != 0) odd_nonzero = 1;
    odd_nonzero = __syncthreads_or(odd_nonzero);
    if (odd_nonzero) {
        // int32 delivery
        for (int i = threadIdx.x; i < NB * 33; i += blockDim.x)
            g_caps[i] = w[i];
    } else {
        // int64 delivery
        const long long* w64 = (const long long*)capsraw;
        for (int i = threadIdx.x; i < NB * 33; i += blockDim.x)
            g_caps[i] = (int)w64[i];
    }
}

// ---------------- zero c ----------------
__global__ void zero_c_kernel() {
    g_c[blockIdx.x * 1024 + threadIdx.x] = 0.0f;
}

// ---------------- generic 64x64 tiled SGEMM with optional embedding gather ----------------
// C[M,N] = A[M,K] @ B[K,N] + bias (row of length N)
// If caps != null: A row for global row r is W_embed row caps[(r>>5)*33 + (r&31)]
// Grid: (N/64, M/64), block 256. All dims divisible by 64/16 by construction.
__global__ void sgemm64_kernel(const float* __restrict__ A, const float* __restrict__ B,
                               const float* __restrict__ bias, float* __restrict__ C,
                               int N, int K, const int* __restrict__ caps)
{
    __shared__ float As[16][64];
    __shared__ float Bs[16][64];
    const int tid = threadIdx.x;
    const int bm = blockIdx.y * 64, bn = blockIdx.x * 64;
    const int tx = tid & 15, ty = tid >> 4;
    const int ar = tid >> 2, ak = (tid & 3) * 4;   // A loader: row ar, 4 consecutive k
    const int bk = tid >> 4, bn0 = (tid & 15) * 4; // B loader: k row bk, 4 consecutive n

    const int row = bm + ar;
    const int src = caps ? caps[(row >> 5) * 33 + (row & 31)] : row;
    const float* Arow = A + (size_t)src * K + ak;
    const float* Bp = B + (size_t)bk * N + bn + bn0;

    float acc[4][4] = {};
    for (int k0 = 0; k0 < K; k0 += 16) {
        float4 av = *(const float4*)(Arow + k0);
        As[ak + 0][ar] = av.x;
        As[ak + 1][ar] = av.y;
        As[ak + 2][ar] = av.z;
        As[ak + 3][ar] = av.w;
        *(float4*)&Bs[bk][bn0] = *(const float4*)(Bp + (size_t)k0 * N);
        __syncthreads();
#pragma unroll
        for (int k = 0; k < 16; k++) {
            float4 a = *(const float4*)&As[k][ty * 4];
            float4 b = *(const float4*)&Bs[k][tx * 4];
            acc[0][0] += a.x * b.x; acc[0][1] += a.x * b.y; acc[0][2] += a.x * b.z; acc[0][3] += a.x * b.w;
            acc[1][0] += a.y * b.x; acc[1][1] += a.y * b.y; acc[1][2] += a.y * b.z; acc[1][3] += a.y * b.w;
            acc[2][0] += a.z * b.x; acc[2][1] += a.z * b.y; acc[2][2] += a.z * b.z; acc[2][3] += a.z * b.w;
            acc[3][0] += a.w * b.x; acc[3][1] += a.w * b.y; acc[3][2] += a.w * b.z; acc[3][3] += a.w * b.w;
        }
        __syncthreads();
    }
    const int cn = bn + tx * 4;
    float4 bb = *(const float4*)(bias + cn);
#pragma unroll
    for (int i = 0; i < 4; i++) {
        float4 o;
        o.x = acc[i][0] + bb.x; o.y = acc[i][1] + bb.y;
        o.z = acc[i][2] + bb.z; o.w = acc[i][3] + bb.w;
        *(float4*)&C[(size_t)(bm + ty * 4 + i) * N + cn] = o;
    }
}

// ---------------- LSTM step: A = hprev@Wh + g_xw[:,t,:] -> gates -> c,h ----------------
// Grid: (512/32=16, 128/32=4), block 256. Tile: 32 rows(n) x 32 cols(j), 4 gates per cell.
__global__ void lstm_step_kernel(const float* __restrict__ Wh, int t)
{
    __shared__ float Hs[16][32];
    __shared__ float Wsm[16][128];   // [k][gate*32 + j]
    const int tid = threadIdx.x;
    const int jb = blockIdx.x * 32, nb = blockIdx.y * 32;
    const float* hprev = t ? (g_hs + (size_t)(t - 1) * NB * HDIM) : g_h0;
    float* hout = g_hs + (size_t)t * NB * HDIM;

    // loaders
    const int hr = tid >> 3, hk0 = (tid & 7) * 2;       // 32 rows x 2 k each
    const int wk = tid >> 4, wc0 = (tid & 15) * 8;      // 16 k rows x 8 cols each
    const int wg = wc0 >> 5, wj0 = wc0 & 31;
    // compute mapping
    const int ty = tid >> 4, tx = tid & 15;             // 16x16 -> 2x2 cells

    float acc[4][2][2] = {};  // [gate][row][col]
    for (int k0 = 0; k0 < HDIM; k0 += 16) {
        float2 hv = *(const float2*)(hprev + (size_t)(nb + hr) * HDIM + k0 + hk0);
        Hs[hk0 + 0][hr] = hv.x;
        Hs[hk0 + 1][hr] = hv.y;
        const float* wp = Wh + (size_t)(k0 + wk) * G4 + wg * HDIM + jb + wj0;
        *(float4*)&Wsm[wk][wc0]     = *(const float4*)(wp);
        *(float4*)&Wsm[wk][wc0 + 4] = *(const float4*)(wp + 4);
        __syncthreads();
#pragma unroll
        for (int k = 0; k < 16; k++) {
            float a0 = Hs[k][ty * 2], a1 = Hs[k][ty * 2 + 1];
#pragma unroll
            for (int g = 0; g < 4; g++) {
                float b0 = Wsm[k][g * 32 + tx * 2];
                float b1 = Wsm[k][g * 32 + tx * 2 + 1];
                acc[g][0][0] += a0 * b0; acc[g][0][1] += a0 * b1;
                acc[g][1][0] += a1 * b0; acc[g][1][1] += a1 * b1;
            }
        }
        __syncthreads();
    }
#pragma unroll
    for (int i = 0; i < 2; i++) {
#pragma unroll
        for (int jj = 0; jj < 2; jj++) {
            const int n = nb + ty * 2 + i;
            const int j = jb + tx * 2 + jj;
            const size_t xb = (size_t)(n * TS + t) * G4 + j;
            float Ai = acc[0][i][jj] + g_xw[xb];
            float Af = acc[1][i][jj] + g_xw[xb + 512];
            float Ao = acc[2][i][jj] + g_xw[xb + 1024];
            float Ag = acc[3][i][jj] + g_xw[xb + 1536];
            float si = 1.0f / (1.0f + expf(-Ai));
            float sf = 1.0f / (1.0f + expf(-Af));
            float so = 1.0f / (1.0f + expf(-Ao));
            float tg = tanhf(Ag);
            const int ci = n * HDIM + j;
            float cn = sf * g_c[ci] + si * tg;
            g_c[ci] = cn;
            hout[ci] = so * tanhf(cn);
        }
    }
}

// ---------------- vocab GEMM + per-chunk logsumexp partials ----------------
// Grid: (500, 64), block 256. Tile 64 rows x 64 vocab cols, K=512.
__global__ void vocab_kernel(const float* __restrict__ Wv, const float* __restrict__ bv)
{
    __shared__ float As[16][64];
    __shared__ float Bs[16][64];
    const int tid = threadIdx.x;
    const int bm = blockIdx.y * 64, bn = blockIdx.x * 64;
    const int tx = tid & 15, ty = tid >> 4;
    const int ar = tid >> 2, ak = (tid & 3) * 4;
    const int bk = tid >> 4, bn0 = (tid & 15) * 4;

    const float* Arow = g_hs + (size_t)(bm + ar) * HDIM + ak;
    const float* Bp = Wv + (size_t)bk * VS + bn + bn0;

    float acc[4][4] = {};
    for (int k0 = 0; k0 < HDIM; k0 += 16) {
        float4 av = *(const float4*)(Arow + k0);
        As[ak + 0][ar] = av.x;
        As[ak + 1][ar] = av.y;
        As[ak + 2][ar] = av.z;
        As[ak + 3][ar] = av.w;
        *(float4*)&Bs[bk][bn0] = *(const float4*)(Bp + (size_t)k0 * VS);
        __syncthreads();
#pragma unroll
        for (int k = 0; k < 16; k++) {
            float4 a = *(const float4*)&As[k][ty * 4];
            float4 b = *(const float4*)&Bs[k][tx * 4];
            acc[0][0] += a.x * b.x; acc[0][1] += a.x * b.y; acc[0][2] += a.x * b.z; acc[0][3] += a.x * b.w;
            acc[1][0] += a.y * b.x; acc[1][1] += a.y * b.y; acc[1][2] += a.y * b.z; acc[1][3] += a.y * b.w;
            acc[2][0] += a.z * b.x; acc[2][1] += a.z * b.y; acc[2][2] += a.z * b.z; acc[2][3] += a.z * b.w;
            acc[3][0] += a.w * b.x; acc[3][1] += a.w * b.y; acc[3][2] += a.w * b.z; acc[3][3] += a.w * b.w;
        }
        __syncthreads();
    }
    float4 bb = *(const float4*)(bv + bn + tx * 4);
#pragma unroll
    for (int i = 0; i < 4; i++) {
        float s0 = acc[i][0] + bb.x;
        float s1 = acc[i][1] + bb.y;
        float s2 = acc[i][2] + bb.z;
        float s3 = acc[i][3] + bb.w;
        float m = fmaxf(fmaxf(s0, s1), fmaxf(s2, s3));
#pragma unroll
        for (int off = 8; off; off >>= 1)
            m = fmaxf(m, __shfl_xor_sync(0xffffffffu, m, off, 16));
        float e = __expf(s0 - m) + __expf(s1 - m) + __expf(s2 - m) + __expf(s3 - m);
#pragma unroll
        for (int off = 8; off; off >>= 1)
            e += __shfl_xor_sync(0xffffffffu, e, off, 16);
        if (tx == 0) {
            const int r = bm + ty * 4 + i;
            g_pmax[r * NVB + blockIdx.x] = m;
            g_psum[r * NVB + blockIdx.x] = e;
        }
    }
}

// ---------------- per-row logsumexp combine + target score + per-CTA partial ----------------
// Grid: 512 CTAs x 256 threads; one warp per row (8 rows/CTA).
__global__ void reduce_kernel(const float* __restrict__ Wv, const float* __restrict__ bv)
{
    const int r = blockIdx.x * 8 + (threadIdx.x >> 5);
    const int lane = threadIdx.x & 31;

    float gm = -INFINITY;
    for (int k = lane; k < NVB; k += 32)
        gm = fmaxf(gm, g_pmax[r * NVB + k]);
#pragma unroll
    for (int off = 16; off; off >>= 1)
        gm = fmaxf(gm, __shfl_xor_sync(0xffffffffu, gm, off));

    float s = 0.0f;
    for (int k = lane; k < NVB; k += 32)
        s += g_psum[r * NVB + k] * expf(g_pmax[r * NVB + k] - gm);
#pragma unroll
    for (int off = 16; off; off >>= 1)
        s += __shfl_xor_sync(0xffffffffu, s, off);

    const int t = r >> 7, n = r & 127;
    const int tgt = g_caps[n * 33 + t + 1];
    float dot = 0.0f;
    for (int k = lane; k < HDIM; k += 32)
        dot += g_hs[(size_t)r * HDIM + k] * Wv[(size_t)k * VS + tgt];
#pragma unroll
    for (int off = 16; off; off >>= 1)
        dot += __shfl_xor_sync(0xffffffffu, dot, off);

    __shared__ float sm[8];
    if (lane == 0) {
        float lse = gm + logf(s);
        float nll = lse - (dot + bv[tgt]);
        sm[threadIdx.x >> 5] = (tgt != 0) ? nll : 0.0f;
    }
    __syncthreads();
    if (threadIdx.x == 0) {
        float tot = 0.0f;
#pragma unroll
        for (int i = 0; i < 8; i++) tot += sm[i];
        g_block[blockIdx.x] = tot;
    }
}

__global__ void final_kernel(float* __restrict__ out)
{
    __shared__ float sm[512];
    sm[threadIdx.x] = g_block[threadIdx.x];
    __syncthreads();
    for (int sstep = 256; sstep; sstep >>= 1) {
        if (threadIdx.x < sstep) sm[threadIdx.x] += sm[threadIdx.x + sstep];
        __syncthreads();
    }
    if (threadIdx.x == 0) out[0] = sm[0] / (float)NB;
}

// ---------------- host ----------------
extern "C" void kernel_launch(void* const* d_in, const int* in_sizes, int n_in,
                              void* d_out, int out_size)
{
    (void)in_sizes; (void)n_in; (void)out_size;
    const float* features = (const float*)d_in[0];
    const void*  captions = d_in[1];
    const float* W_proj   = (const float*)d_in[2];
    const float* b_proj   = (const float*)d_in[3];
    const float* W_embed  = (const float*)d_in[4];
    const float* Wx       = (const float*)d_in[5];
    const float* Wh       = (const float*)d_in[6];
    const float* b        = (const float*)d_in[7];
    const float* W_vocab  = (const float*)d_in[8];
    const float* b_vocab  = (const float*)d_in[9];

    float *h0p = nullptr, *xwp = nullptr;
    int *capsp = nullptr;
    cudaGetSymbolAddress((void**)&h0p, g_h0);
    cudaGetSymbolAddress((void**)&xwp, g_xw);
    cudaGetSymbolAddress((void**)&capsp, g_caps);

    decode_caps_kernel<<<1, 256>>>(captions);
    zero_c_kernel<<<64, 1024>>>();

    // h0 = features @ W_proj + b_proj   (M=128, K=1280, N=512)
    sgemm64_kernel<<<dim3(HDIM / 64, NB / 64), 256>>>(features, W_proj, b_proj, h0p,
                                                      HDIM, DFEAT, nullptr);
    // XW = embed(captions_in) @ Wx + b  (M=4096 rows (n*32+t), K=256, N=2048)
    sgemm64_kernel<<<dim3(G4 / 64, RTOT / 64), 256>>>(W_embed, Wx, b, xwp,
                                                      G4, WDIM, capsp);
    // sequential LSTM
    for (int t = 0; t < TS; t++)
        lstm_step_kernel<<<dim3(HDIM / 32, NB / 32), 256>>>(Wh, t);

    // fused vocab GEMM + chunked logsumexp
    vocab_kernel<<<dim3(NVB, RTOT / 64), 256>>>(W_vocab, b_vocab);

    // combine + target scores + deterministic reduction
    reduce_kernel<<<512, 256>>>(W_vocab, b_vocab);
    final_kernel<<<1, 512>>>((float*)d_out);
}